// round 4
// baseline (speedup 1.0000x reference)
#include <cuda_runtime.h>
#include <cstdint>
#include <cstddef>

#define E_   8
#define T_   2048
#define DIN_ 2048
#define H_   1408

// ---------------- device scratch (allocation-free) ----------------
__device__ float g_gateT[(size_t)E_ * H_ * DIN_];   // [e][h][d], tf32-rounded
__device__ float g_downT[(size_t)E_ * H_ * DIN_];   // [e][h][d], tf32-rounded
__device__ float g_upT  [(size_t)E_ * DIN_ * H_];   // [e][d][h], tf32-rounded
__device__ float g_xr   [(size_t)E_ * T_ * DIN_];   // [e][t][d], tf32-rounded
__device__ float g_hbuf [(size_t)E_ * T_ * H_];     // [e][t][h], tf32-rounded

// ---------------- helpers ----------------
__device__ __forceinline__ uint32_t smem_u32(const void* p) {
    uint32_t a;
    asm("{ .reg .u64 t; cvta.to.shared.u64 t, %1; cvt.u32.u64 %0, t; }" : "=r"(a) : "l"(p));
    return a;
}
__device__ __forceinline__ float tf32_val(float f) {
    uint32_t r;
    asm("cvt.rna.tf32.f32 %0, %1;" : "=r"(r) : "f"(f));
    return __uint_as_float(r);
}
__device__ __forceinline__ void cp16(uint32_t s, const void* g) {
    asm volatile("cp.async.cg.shared.global [%0], [%1], 16;" :: "r"(s), "l"(g));
}
#define CP_COMMIT() asm volatile("cp.async.commit_group;" ::: "memory")
#define CP_WAIT(n)  asm volatile("cp.async.wait_group %0;" :: "n"(n) : "memory")

// m16n8k8 tf32 row.col, fp32 accum
__device__ __forceinline__ void mma8(float* cc, const uint32_t* a, const uint32_t* b) {
    asm volatile(
        "mma.sync.aligned.m16n8k8.row.col.f32.tf32.tf32.f32 "
        "{%0,%1,%2,%3}, {%4,%5,%6,%7}, {%8,%9}, {%0,%1,%2,%3};"
        : "+f"(cc[0]), "+f"(cc[1]), "+f"(cc[2]), "+f"(cc[3])
        : "r"(a[0]), "r"(a[1]), "r"(a[2]), "r"(a[3]), "r"(b[0]), "r"(b[1]));
}

// smem row pitch: 32 floats padded to 36 (144B: 16B-aligned, conflict-free frags)
#define PITCH 36
#define TILE_FLOATS (128 * PITCH)          // 4608 floats per 128x32 tile

// ---------------- elementwise tf32 round ----------------
__global__ void round_tf32_kernel(const float4* __restrict__ in, float4* __restrict__ out, int n4) {
    int i = blockIdx.x * blockDim.x + threadIdx.x;
    if (i < n4) {
        float4 v = in[i];
        v.x = tf32_val(v.x); v.y = tf32_val(v.y);
        v.z = tf32_val(v.z); v.w = tf32_val(v.w);
        out[i] = v;
    }
}

// ---------------- transpose + tf32 round: in[e][r][c] -> out[e][c][r] ----------------
__global__ void transpose_tf32_kernel(const float* __restrict__ in, float* __restrict__ out,
                                      int R, int C) {
    __shared__ float tile[32][33];
    int e = blockIdx.z;
    int c0 = blockIdx.x * 32, r0 = blockIdx.y * 32;
    const float* inp = in + (size_t)e * R * C;
    float* outp = out + (size_t)e * R * C;
    int tx = threadIdx.x, ty = threadIdx.y;
#pragma unroll
    for (int i = 0; i < 32; i += 8)
        tile[ty + i][tx] = tf32_val(inp[(size_t)(r0 + ty + i) * C + c0 + tx]);
    __syncthreads();
#pragma unroll
    for (int i = 0; i < 32; i += 8)
        outp[(size_t)(c0 + ty + i) * R + r0 + tx] = tile[tx][ty + i];
}

// ---------------- k1: fused gate+down GEMM + SwiGLU ----------------
// acc_g[h,t] = sum_d gateT[h,d]*xr[t,d]; acc_d likewise; hbuf[t,h]=tf32(silu(g)*u)
// smem per stage: Ag[128][36] | Ad[128][36] | Bx[128][36]; 2 stages
__global__ __launch_bounds__(256, 1) void k1_gemm(const float* __restrict__ xr,
                                                  const float* __restrict__ gT,
                                                  const float* __restrict__ dT,
                                                  float* __restrict__ hb) {
    extern __shared__ float smf[];
    int tid = threadIdx.x, lane = tid & 31, wid = tid >> 5;
    int wm = wid & 1, wn = wid >> 1;       // warp grid 2(M) x 4(N)
    int r = lane >> 2, c = lane & 3;

    int bid = blockIdx.x;
    int e = bid / (11 * 16);
    int rem = bid % (11 * 16);
    int h0 = (rem >> 4) * 128;
    int t0 = (rem & 15) * 128;

    const float* gp = gT + (size_t)e * H_ * DIN_ + (size_t)h0 * DIN_;
    const float* dp = dT + (size_t)e * H_ * DIN_ + (size_t)h0 * DIN_;
    const float* xp = xr + (size_t)e * T_ * DIN_ + (size_t)t0 * DIN_;

    float ag[4][4][4], ad[4][4][4];
#pragma unroll
    for (int mt = 0; mt < 4; mt++)
#pragma unroll
        for (int nt = 0; nt < 4; nt++)
#pragma unroll
            for (int k = 0; k < 4; k++) { ag[mt][nt][k] = 0.f; ad[mt][nt][k] = 0.f; }

    uint32_t sbase = smem_u32(smf);
    const int stageStride = 3 * TILE_FLOATS;          // floats

    auto fill = [&](int s, int kc) {
        uint32_t stg = sbase + (uint32_t)(s * stageStride * 4);
#pragma unroll
        for (int i = 0; i < 12; i++) {
            int idx = tid + i * 256;                   // 0..3071
            int region = idx >> 10;                    // 0=Ag 1=Ad 2=Bx
            int li = idx & 1023;
            int row = li >> 3, c16 = li & 7;
            const float* src = (region == 0) ? gp : (region == 1) ? dp : xp;
            const float* gsrc = src + (size_t)row * DIN_ + kc * 32 + c16 * 4;
            uint32_t soff = stg + (uint32_t)region * (TILE_FLOATS * 4) + row * (PITCH * 4) + c16 * 16;
            cp16(soff, gsrc);
        }
    };

    auto compute = [&](int s) {
        const float* stg = smf + s * stageStride;
        const uint32_t* Ag = (const uint32_t*)stg;
        const uint32_t* Ad = (const uint32_t*)(stg + TILE_FLOATS);
        const uint32_t* Bx = (const uint32_t*)(stg + 2 * TILE_FLOATS);
#pragma unroll
        for (int ks = 0; ks < 4; ks++) {
            uint32_t bf[4][2];
#pragma unroll
            for (int nt = 0; nt < 4; nt++) {
                const uint32_t* bp = Bx + (wn * 32 + nt * 8 + r) * PITCH + ks * 8 + c;
                bf[nt][0] = bp[0]; bf[nt][1] = bp[4];
            }
            uint32_t af[4][4];
#pragma unroll
            for (int mt = 0; mt < 4; mt++) {
                const uint32_t* ap = Ag + (wm * 64 + mt * 16 + r) * PITCH + ks * 8 + c;
                af[mt][0] = ap[0]; af[mt][1] = ap[8 * PITCH];
                af[mt][2] = ap[4]; af[mt][3] = ap[8 * PITCH + 4];
            }
#pragma unroll
            for (int mt = 0; mt < 4; mt++)
#pragma unroll
                for (int nt = 0; nt < 4; nt++) mma8(ag[mt][nt], af[mt], bf[nt]);
#pragma unroll
            for (int mt = 0; mt < 4; mt++) {
                const uint32_t* ap = Ad + (wm * 64 + mt * 16 + r) * PITCH + ks * 8 + c;
                af[mt][0] = ap[0]; af[mt][1] = ap[8 * PITCH];
                af[mt][2] = ap[4]; af[mt][3] = ap[8 * PITCH + 4];
            }
#pragma unroll
            for (int mt = 0; mt < 4; mt++)
#pragma unroll
                for (int nt = 0; nt < 4; nt++) mma8(ad[mt][nt], af[mt], bf[nt]);
        }
    };

    const int NC = DIN_ / 32;   // 64
    fill(0, 0); CP_COMMIT();
    for (int kc = 0; kc < NC; kc++) {
        if (kc + 1 < NC) {
            fill((kc + 1) & 1, kc + 1); CP_COMMIT();
            CP_WAIT(1);
        } else {
            CP_WAIT(0);
        }
        __syncthreads();
        compute(kc & 1);
        __syncthreads();
    }

    // SwiGLU epilogue -> hbuf[t][h] (tf32-rounded)
    float* hbb = hb + (size_t)e * T_ * H_;
#pragma unroll
    for (int mt = 0; mt < 4; mt++)
#pragma unroll
        for (int nt = 0; nt < 4; nt++) {
            int t = t0 + wn * 32 + nt * 8 + 2 * c;
#pragma unroll
            for (int h2 = 0; h2 < 2; h2++) {
                int hg = h0 + wm * 64 + mt * 16 + r + h2 * 8;
                float g0 = ag[mt][nt][h2 * 2 + 0], g1 = ag[mt][nt][h2 * 2 + 1];
                float u0 = ad[mt][nt][h2 * 2 + 0], u1 = ad[mt][nt][h2 * 2 + 1];
                float v0 = tf32_val(g0 / (1.0f + __expf(-g0)) * u0);
                float v1 = tf32_val(g1 / (1.0f + __expf(-g1)) * u1);
                hbb[(size_t)t * H_ + hg] = v0;
                hbb[(size_t)(t + 1) * H_ + hg] = v1;
            }
        }
}

// ---------------- k2: out[t,d] = sum_h hbuf[t,h]*upT[d,h] ----------------
__global__ __launch_bounds__(256, 1) void k2_gemm(const float* __restrict__ hbv,
                                                  const float* __restrict__ uT,
                                                  float* __restrict__ out) {
    extern __shared__ float smf[];
    int tid = threadIdx.x, lane = tid & 31, wid = tid >> 5;
    int wm = wid & 1, wn = wid >> 1;
    int r = lane >> 2, c = lane & 3;

    int bid = blockIdx.x;
    int e = bid / (16 * 16);
    int rem = bid % (16 * 16);
    int d0 = (rem >> 4) * 128;
    int t0 = (rem & 15) * 128;

    const float* up = uT + (size_t)e * DIN_ * H_ + (size_t)d0 * H_;
    const float* hp = hbv + (size_t)e * T_ * H_ + (size_t)t0 * H_;

    float acc[4][4][4];
#pragma unroll
    for (int mt = 0; mt < 4; mt++)
#pragma unroll
        for (int nt = 0; nt < 4; nt++)
#pragma unroll
            for (int k = 0; k < 4; k++) acc[mt][nt][k] = 0.f;

    uint32_t sbase = smem_u32(smf);
    const int stageStride = 2 * TILE_FLOATS;

    auto fill = [&](int s, int kc) {
        uint32_t stg = sbase + (uint32_t)(s * stageStride * 4);
#pragma unroll
        for (int i = 0; i < 8; i++) {
            int idx = tid + i * 256;                   // 0..2047
            int region = idx >> 10;                    // 0=A(up) 1=B(hbuf)
            int li = idx & 1023;
            int row = li >> 3, c16 = li & 7;
            const float* src = region ? hp : up;
            const float* gsrc = src + (size_t)row * H_ + kc * 32 + c16 * 4;
            uint32_t soff = stg + (uint32_t)region * (TILE_FLOATS * 4) + row * (PITCH * 4) + c16 * 16;
            cp16(soff, gsrc);
        }
    };

    auto compute = [&](int s) {
        const float* stg = smf + s * stageStride;
        const uint32_t* A = (const uint32_t*)stg;
        const uint32_t* B = (const uint32_t*)(stg + TILE_FLOATS);
#pragma unroll
        for (int ks = 0; ks < 4; ks++) {
            uint32_t bf[4][2];
#pragma unroll
            for (int nt = 0; nt < 4; nt++) {
                const uint32_t* bp = B + (wn * 32 + nt * 8 + r) * PITCH + ks * 8 + c;
                bf[nt][0] = bp[0]; bf[nt][1] = bp[4];
            }
            uint32_t af[4][4];
#pragma unroll
            for (int mt = 0; mt < 4; mt++) {
                const uint32_t* ap = A + (wm * 64 + mt * 16 + r) * PITCH + ks * 8 + c;
                af[mt][0] = ap[0]; af[mt][1] = ap[8 * PITCH];
                af[mt][2] = ap[4]; af[mt][3] = ap[8 * PITCH + 4];
            }
#pragma unroll
            for (int mt = 0; mt < 4; mt++)
#pragma unroll
                for (int nt = 0; nt < 4; nt++) mma8(acc[mt][nt], af[mt], bf[nt]);
        }
    };

    const int NC = H_ / 32;   // 44
    fill(0, 0); CP_COMMIT();
    for (int kc = 0; kc < NC; kc++) {
        if (kc + 1 < NC) {
            fill((kc + 1) & 1, kc + 1); CP_COMMIT();
            CP_WAIT(1);
        } else {
            CP_WAIT(0);
        }
        __syncthreads();
        compute(kc & 1);
        __syncthreads();
    }

    float* ob = out + (size_t)e * T_ * DIN_;
#pragma unroll
    for (int mt = 0; mt < 4; mt++)
#pragma unroll
        for (int nt = 0; nt < 4; nt++) {
            int t = t0 + wn * 32 + nt * 8 + 2 * c;
#pragma unroll
            for (int h2 = 0; h2 < 2; h2++) {
                int dg = d0 + wm * 64 + mt * 16 + r + h2 * 8;
                ob[(size_t)t * DIN_ + dg]       = acc[mt][nt][h2 * 2 + 0];
                ob[(size_t)(t + 1) * DIN_ + dg] = acc[mt][nt][h2 * 2 + 1];
            }
        }
}

// ---------------- launch ----------------
extern "C" void kernel_launch(void* const* d_in, const int* in_sizes, int n_in,
                              void* d_out, int out_size) {
    const float* x    = (const float*)d_in[0];
    const float* gate = (const float*)d_in[1];
    const float* down = (const float*)d_in[2];
    const float* up   = (const float*)d_in[3];
    float* out = (float*)d_out;

    float *gT, *dT, *uT, *xr, *hb;
    cudaGetSymbolAddress((void**)&gT, g_gateT);
    cudaGetSymbolAddress((void**)&dT, g_downT);
    cudaGetSymbolAddress((void**)&uT, g_upT);
    cudaGetSymbolAddress((void**)&xr, g_xr);
    cudaGetSymbolAddress((void**)&hb, g_hbuf);

    const int k1_smem = 2 * 3 * TILE_FLOATS * 4;   // 110592
    const int k2_smem = 2 * 2 * TILE_FLOATS * 4;   // 73728
    cudaFuncSetAttribute(k1_gemm, cudaFuncAttributeMaxDynamicSharedMemorySize, k1_smem);
    cudaFuncSetAttribute(k2_gemm, cudaFuncAttributeMaxDynamicSharedMemorySize, k2_smem);

    // pre-pass: round x, transpose+round weights
    int n4 = E_ * T_ * DIN_ / 4;
    round_tf32_kernel<<<(n4 + 255) / 256, 256>>>((const float4*)x, (float4*)xr, n4);
    dim3 tb(32, 8);
    transpose_tf32_kernel<<<dim3(H_ / 32, DIN_ / 32, E_), tb>>>(gate, gT, DIN_, H_);
    transpose_tf32_kernel<<<dim3(H_ / 32, DIN_ / 32, E_), tb>>>(down, dT, DIN_, H_);
    transpose_tf32_kernel<<<dim3(DIN_ / 32, H_ / 32, E_), tb>>>(up, uT, H_, DIN_);

    k1_gemm<<<E_ * (H_ / 128) * (T_ / 128), 256, k1_smem>>>(xr, gT, dT, hb);
    k2_gemm<<<E_ * (DIN_ / 128) * (T_ / 128), 256, k2_smem>>>(hb, uT, out);
}

// round 6
// speedup vs baseline: 1.2763x; 1.2763x over previous
#include <cuda_runtime.h>
#include <cstdint>
#include <cstddef>

#define E_   8
#define T_   2048
#define DIN_ 2048
#define H_   1408

// tiles
#define MT   128          // M tile
#define NT   128          // N tile (tokens)
#define KCH  32           // K chunk
#define HTILES   (H_ / MT)     // 11
#define DTILES   (DIN_ / MT)   // 16
#define TTILES   (T_ / NT)     // 16
#define KC1  (DIN_ / KCH)      // 64  (k1 reduction)
#define KC2  (H_ / KCH)        // 44  (k2 reduction)

// frag tile sizes (floats) — both 128x32 tiles are 4096 floats (16KB)
#define ATILE_F 4096
#define BTILE_F 4096

// ---------------- device scratch (allocation-free) ----------------
__device__ float g_wfG[(size_t)E_ * HTILES * KC1 * ATILE_F];  // gateT frag-major
__device__ float g_wfD[(size_t)E_ * HTILES * KC1 * ATILE_F];  // downT frag-major
__device__ float g_wfU[(size_t)E_ * DTILES * KC2 * ATILE_F];  // upT   frag-major
__device__ float g_xf [(size_t)E_ * TTILES * KC1 * BTILE_F];  // x     frag-major (B)
__device__ float g_hf [(size_t)E_ * TTILES * KC2 * BTILE_F];  // h     frag-major (B)

// ---------------- helpers ----------------
__device__ __forceinline__ uint32_t smem_u32(const void* p) {
    uint32_t a;
    asm("{ .reg .u64 t; cvta.to.shared.u64 t, %1; cvt.u32.u64 %0, t; }" : "=r"(a) : "l"(p));
    return a;
}
__device__ __forceinline__ float tf32_val(float f) {
    uint32_t r;
    asm("cvt.rna.tf32.f32 %0, %1;" : "=r"(r) : "f"(f));
    return __uint_as_float(r);
}
__device__ __forceinline__ void cp16(uint32_t s, const void* g) {
    asm volatile("cp.async.cg.shared.global [%0], [%1], 16;" :: "r"(s), "l"(g));
}
#define CP_COMMIT() asm volatile("cp.async.commit_group;" ::: "memory")
#define CP_WAIT(n)  asm volatile("cp.async.wait_group %0;" :: "n"(n) : "memory")

// m16n8k8 tf32 row.col, fp32 accum
__device__ __forceinline__ void mma8(float* cc, const uint32_t* a, const uint32_t* b) {
    asm volatile(
        "mma.sync.aligned.m16n8k8.row.col.f32.tf32.tf32.f32 "
        "{%0,%1,%2,%3}, {%4,%5,%6,%7}, {%8,%9}, {%0,%1,%2,%3};"
        : "+f"(cc[0]), "+f"(cc[1]), "+f"(cc[2]), "+f"(cc[3])
        : "r"(a[0]), "r"(a[1]), "r"(a[2]), "r"(a[3]), "r"(b[0]), "r"(b[1]));
}

// ---------------- prep: transpose src[K][M] -> A-frag tiles, tf32-rounded ----
// A[m][k] = src[k][m].  Per 128x32 tile, float4 f = (mb*4 + ks)*32 + lane:
//   {A[mb*16+r][ks*8+c], A[mb*16+8+r][ks*8+c], A[mb*16+r][ks*8+c+4], A[mb*16+8+r][ks*8+c+4]}
__global__ void prep_w_kernel(const float* __restrict__ src, float4* __restrict__ dst,
                              int R, int C, int Mtiles, int Kchunks) {
    __shared__ float ts[32][132];
    int e = blockIdx.z, mt = blockIdx.y, kc = blockIdx.x;
    int tid = threadIdx.x;
    const float* sp = src + (size_t)e * R * C + (size_t)(kc * 32) * C + mt * 128;
#pragma unroll
    for (int i = 0; i < 16; i++) {
        int idx = tid + i * 256;
        int kk = idx >> 7, mm = idx & 127;
        ts[kk][mm] = tf32_val(sp[(size_t)kk * C + mm]);
    }
    __syncthreads();
    float4* dp = dst + ((size_t)(e * Mtiles + mt) * Kchunks + kc) * 1024;
#pragma unroll
    for (int i = 0; i < 4; i++) {
        int f = tid + i * 256;
        int lane = f & 31, ks = (f >> 5) & 3, mb = f >> 7;
        int r = lane >> 2, c = lane & 3;
        float4 v;
        v.x = ts[ks * 8 + c][mb * 16 + r];
        v.y = ts[ks * 8 + c][mb * 16 + 8 + r];
        v.z = ts[ks * 8 + c + 4][mb * 16 + r];
        v.w = ts[ks * 8 + c + 4][mb * 16 + 8 + r];
        dp[f] = v;
    }
}

// ---------------- prep: x[t][k] -> B-frag tiles, tf32-rounded ----------------
// Per 128x32 tile, float2 f = (n8*4 + ks)*32 + lane:
//   {B[n8*8+r][ks*8+c], B[n8*8+r][ks*8+c+4]}   (2048 float2 = 4096 floats)
__global__ void prep_x_kernel(const float* __restrict__ src, float2* __restrict__ dst) {
    __shared__ float ts[128][33];
    int e = blockIdx.z, tb = blockIdx.y, kc = blockIdx.x;
    int tid = threadIdx.x;
    const float* sp = src + (size_t)e * T_ * DIN_ + (size_t)(tb * 128) * DIN_ + kc * 32;
#pragma unroll
    for (int i = 0; i < 16; i++) {
        int idx = tid + i * 256;
        int tt = idx >> 5, kk = idx & 31;
        ts[tt][kk] = tf32_val(sp[(size_t)tt * DIN_ + kk]);
    }
    __syncthreads();
    float2* dp = dst + ((size_t)(e * TTILES + tb) * KC1 + kc) * 2048;
#pragma unroll
    for (int i = 0; i < 8; i++) {
        int f = tid + i * 256;
        int lane = f & 31, ks = (f >> 5) & 3, n8 = f >> 7;
        int r = lane >> 2, c = lane & 3;
        float2 v;
        v.x = ts[n8 * 8 + r][ks * 8 + c];
        v.y = ts[n8 * 8 + r][ks * 8 + c + 4];
        dp[f] = v;
    }
}

// ---------------- k1: fused gate+down GEMM + SwiGLU -> hfrag --------------
// smem per stage: Ag(16KB) Ad(16KB) Bx(16KB) = 48KB, 2 stages = 96KB
#define K1_STAGE_F (2 * ATILE_F + BTILE_F)    // 12288 floats
__global__ __launch_bounds__(256, 1) void k1_gemm(const float* __restrict__ xf,
                                                  const float* __restrict__ gF,
                                                  const float* __restrict__ dF,
                                                  float* __restrict__ hf) {
    extern __shared__ float smf[];
    int tid = threadIdx.x, lane = tid & 31, wid = tid >> 5;
    int wm = wid & 1, wn = wid >> 1;       // 2(M) x 4(N) warp grid
    int r = lane >> 2, c = lane & 3;

    int bid = blockIdx.x;
    int e = bid / (HTILES * TTILES);
    int rem = bid % (HTILES * TTILES);
    int ht = rem >> 4;                      // h tile (11)
    int tb = rem & 15;                      // t tile (16)
    int h0 = ht * 128;

    const float* gp = gF + ((size_t)(e * HTILES + ht) * KC1) * ATILE_F;
    const float* dp = dF + ((size_t)(e * HTILES + ht) * KC1) * ATILE_F;
    const float* xp = xf + ((size_t)(e * TTILES + tb) * KC1) * BTILE_F;

    float ag[4][4][4], ad[4][4][4];
#pragma unroll
    for (int mt = 0; mt < 4; mt++)
#pragma unroll
        for (int nt = 0; nt < 4; nt++)
#pragma unroll
            for (int k = 0; k < 4; k++) { ag[mt][nt][k] = 0.f; ad[mt][nt][k] = 0.f; }

    uint32_t sbase = smem_u32(smf);

    auto fill = [&](int s, int kc) {
        uint32_t stg = sbase + (uint32_t)(s * K1_STAGE_F * 4);
        const float* ga = gp + (size_t)kc * ATILE_F;
        const float* da = dp + (size_t)kc * ATILE_F;
        const float* xa = xp + (size_t)kc * BTILE_F;
#pragma unroll
        for (int i = 0; i < 12; i++) {
            int idx = tid + i * 256;                 // 0..3071 float4s
            if (idx < 1024)       cp16(stg + idx * 16, ga + idx * 4);
            else if (idx < 2048)  cp16(stg + idx * 16, da + (idx - 1024) * 4);
            else                  cp16(stg + idx * 16, xa + (idx - 2048) * 4);
        }
    };

    auto compute = [&](int s) {
        const float* stg = smf + s * K1_STAGE_F;
        const float4* Ag = (const float4*)stg;
        const float4* Ad = (const float4*)(stg + ATILE_F);
        const float2* Bx = (const float2*)(stg + 2 * ATILE_F);
#pragma unroll
        for (int ks = 0; ks < 4; ks++) {
            float2 bf[4];
#pragma unroll
            for (int nt = 0; nt < 4; nt++)
                bf[nt] = Bx[((wn * 4 + nt) * 4 + ks) * 32 + lane];
            float4 af[4];
#pragma unroll
            for (int mt = 0; mt < 4; mt++)
                af[mt] = Ag[((wm * 4 + mt) * 4 + ks) * 32 + lane];
#pragma unroll
            for (int mt = 0; mt < 4; mt++)
#pragma unroll
                for (int nt = 0; nt < 4; nt++)
                    mma8(ag[mt][nt], (const uint32_t*)&af[mt], (const uint32_t*)&bf[nt]);
#pragma unroll
            for (int mt = 0; mt < 4; mt++)
                af[mt] = Ad[((wm * 4 + mt) * 4 + ks) * 32 + lane];
#pragma unroll
            for (int mt = 0; mt < 4; mt++)
#pragma unroll
                for (int nt = 0; nt < 4; nt++)
                    mma8(ad[mt][nt], (const uint32_t*)&af[mt], (const uint32_t*)&bf[nt]);
        }
    };

    fill(0, 0); CP_COMMIT();
    for (int kc = 0; kc < KC1; kc++) {
        if (kc + 1 < KC1) { fill((kc + 1) & 1, kc + 1); CP_COMMIT(); CP_WAIT(1); }
        else              { CP_WAIT(0); }
        __syncthreads();
        compute(kc & 1);
        __syncthreads();
    }

    // SwiGLU epilogue -> hfrag[e][tb][kc2][frag] (tf32-rounded), B-frag order for k2
    float* hbase = hf + ((size_t)(e * TTILES + tb) * KC2) * BTILE_F;
#pragma unroll
    for (int mt = 0; mt < 4; mt++)
#pragma unroll
        for (int nt = 0; nt < 4; nt++) {
            int n8 = wn * 4 + nt;
#pragma unroll
            for (int q = 0; q < 4; q++) {
                int rr = 2 * c + (q & 1);                       // t within n8 block
                int h = h0 + wm * 64 + mt * 16 + r + (q >> 1) * 8;
                int kc2 = h >> 5, hh = h & 31;
                int ks2 = hh >> 3, cC = hh & 7;
                int j = cC >> 2, c2 = cC & 3;
                float g = ag[mt][nt][q], u = ad[mt][nt][q];
                float v = tf32_val(g / (1.0f + __expf(-g)) * u);
                hbase[(size_t)kc2 * BTILE_F + (((n8 * 4 + ks2) * 32 + rr * 4 + c2) * 2 + j)] = v;
            }
        }
}

// ---------------- k2: out[t,d] = sum_h h[t,h] * up[h,d] -------------------
// smem per stage: A(16KB) B(16KB) = 32KB, 2 stages = 64KB -> 2 CTAs/SM (128KB)
#define K2_STAGE_F (ATILE_F + BTILE_F)        // 8192 floats
__global__ __launch_bounds__(256, 2) void k2_gemm(const float* __restrict__ hf,
                                                  const float* __restrict__ uF,
                                                  float* __restrict__ out) {
    extern __shared__ float smf[];
    int tid = threadIdx.x, lane = tid & 31, wid = tid >> 5;
    int wm = wid & 1, wn = wid >> 1;
    int r = lane >> 2, c = lane & 3;

    int bid = blockIdx.x;
    int e = bid / (DTILES * TTILES);
    int rem = bid % (DTILES * TTILES);
    int dt = rem >> 4;
    int tb = rem & 15;
    int d0 = dt * 128, t0 = tb * 128;

    const float* up = uF + ((size_t)(e * DTILES + dt) * KC2) * ATILE_F;
    const float* hp = hf + ((size_t)(e * TTILES + tb) * KC2) * BTILE_F;

    float acc[4][4][4];
#pragma unroll
    for (int mt = 0; mt < 4; mt++)
#pragma unroll
        for (int nt = 0; nt < 4; nt++)
#pragma unroll
            for (int k = 0; k < 4; k++) acc[mt][nt][k] = 0.f;

    uint32_t sbase = smem_u32(smf);

    auto fill = [&](int s, int kc) {
        uint32_t stg = sbase + (uint32_t)(s * K2_STAGE_F * 4);
        const float* ua = up + (size_t)kc * ATILE_F;
        const float* ha = hp + (size_t)kc * BTILE_F;
#pragma unroll
        for (int i = 0; i < 8; i++) {
            int idx = tid + i * 256;                 // 0..2047 float4s
            if (idx < 1024) cp16(stg + idx * 16, ua + idx * 4);
            else            cp16(stg + idx * 16, ha + (idx - 1024) * 4);
        }
    };

    auto compute = [&](int s) {
        const float* stg = smf + s * K2_STAGE_F;
        const float4* A = (const float4*)stg;
        const float2* B = (const float2*)(stg + ATILE_F);
#pragma unroll
        for (int ks = 0; ks < 4; ks++) {
            float2 bf[4];
#pragma unroll
            for (int nt = 0; nt < 4; nt++)
                bf[nt] = B[((wn * 4 + nt) * 4 + ks) * 32 + lane];
            float4 af[4];
#pragma unroll
            for (int mt = 0; mt < 4; mt++)
                af[mt] = A[((wm * 4 + mt) * 4 + ks) * 32 + lane];
#pragma unroll
            for (int mt = 0; mt < 4; mt++)
#pragma unroll
                for (int nt = 0; nt < 4; nt++)
                    mma8(acc[mt][nt], (const uint32_t*)&af[mt], (const uint32_t*)&bf[nt]);
        }
    };

    fill(0, 0); CP_COMMIT();
    for (int kc = 0; kc < KC2; kc++) {
        if (kc + 1 < KC2) { fill((kc + 1) & 1, kc + 1); CP_COMMIT(); CP_WAIT(1); }
        else              { CP_WAIT(0); }
        __syncthreads();
        compute(kc & 1);
        __syncthreads();
    }

    float* ob = out + (size_t)e * T_ * DIN_;
#pragma unroll
    for (int mt = 0; mt < 4; mt++)
#pragma unroll
        for (int nt = 0; nt < 4; nt++) {
            int t = t0 + wn * 32 + nt * 8 + 2 * c;
#pragma unroll
            for (int h2 = 0; h2 < 2; h2++) {
                int dg = d0 + wm * 64 + mt * 16 + r + h2 * 8;
                ob[(size_t)t * DIN_ + dg]       = acc[mt][nt][h2 * 2 + 0];
                ob[(size_t)(t + 1) * DIN_ + dg] = acc[mt][nt][h2 * 2 + 1];
            }
        }
}

// ---------------- launch ----------------
extern "C" void kernel_launch(void* const* d_in, const int* in_sizes, int n_in,
                              void* d_out, int out_size) {
    const float* x    = (const float*)d_in[0];
    const float* gate = (const float*)d_in[1];
    const float* down = (const float*)d_in[2];
    const float* up   = (const float*)d_in[3];
    float* out = (float*)d_out;

    float *gF, *dF, *uF, *xF, *hF;
    cudaGetSymbolAddress((void**)&gF, g_wfG);
    cudaGetSymbolAddress((void**)&dF, g_wfD);
    cudaGetSymbolAddress((void**)&uF, g_wfU);
    cudaGetSymbolAddress((void**)&xF, g_xf);
    cudaGetSymbolAddress((void**)&hF, g_hf);

    const int k1_smem = 2 * K1_STAGE_F * 4;   // 98304
    const int k2_smem = 2 * K2_STAGE_F * 4;   // 65536
    cudaFuncSetAttribute(k1_gemm, cudaFuncAttributeMaxDynamicSharedMemorySize, k1_smem);
    cudaFuncSetAttribute(k2_gemm, cudaFuncAttributeMaxDynamicSharedMemorySize, k2_smem);

    // pre-pass: frag-major staging (all tf32-rounded)
    prep_w_kernel<<<dim3(KC1, HTILES, E_), 256>>>(gate, (float4*)gF, DIN_, H_, HTILES, KC1);
    prep_w_kernel<<<dim3(KC1, HTILES, E_), 256>>>(down, (float4*)dF, DIN_, H_, HTILES, KC1);
    prep_w_kernel<<<dim3(KC2, DTILES, E_), 256>>>(up, (float4*)uF, H_, DIN_, DTILES, KC2);
    prep_x_kernel<<<dim3(KC1, TTILES, E_), 256>>>(x, (float2*)xF);

    k1_gemm<<<E_ * HTILES * TTILES, 256, k1_smem>>>(xF, gF, dF, hF);
    k2_gemm<<<E_ * DTILES * TTILES, 256, k2_smem>>>(hF, uF, out);
}

// round 7
// speedup vs baseline: 2.1401x; 1.6768x over previous
#include <cuda_runtime.h>
#include <cuda_fp16.h>
#include <cstdint>
#include <cstddef>

#define E_   8
#define T_   2048
#define DIN_ 2048
#define H_   1408

#define HTILES 11
#define DTILES 16
#define TTILES 16
#define KC1 64          // DIN_/32
#define KC2 44          // H_/32

// fragment-major fp16 tiles, in uint32 units (one u32 = half2)
#define ATILE_U 2048    // 128(M) x 32(K) fp16 A tile = 8KB = 512 uint4
#define BTILE_U 2048    // 128(N) x 32(K) fp16 B tile = 8KB = 1024 uint2

// ---------------- device scratch (allocation-free) ----------------
__device__ uint32_t g_wfG[(size_t)E_ * HTILES * KC1 * ATILE_U];
__device__ uint32_t g_wfD[(size_t)E_ * HTILES * KC1 * ATILE_U];
__device__ uint32_t g_wfU[(size_t)E_ * DTILES * KC2 * ATILE_U];
__device__ uint32_t g_xf [(size_t)E_ * TTILES * KC1 * BTILE_U];
__device__ uint32_t g_hf [(size_t)E_ * TTILES * KC2 * BTILE_U];

// ---------------- helpers ----------------
__device__ __forceinline__ uint32_t smem_u32(const void* p) {
    uint32_t a;
    asm("{ .reg .u64 t; cvta.to.shared.u64 t, %1; cvt.u32.u64 %0, t; }" : "=r"(a) : "l"(p));
    return a;
}
__device__ __forceinline__ uint32_t pack2(float lo, float hi) {
    __half2 h = __floats2half2_rn(lo, hi);
    return *(const uint32_t*)&h;
}
__device__ __forceinline__ void cp16(uint32_t s, const void* g) {
    asm volatile("cp.async.cg.shared.global [%0], [%1], 16;" :: "r"(s), "l"(g));
}
#define CP_COMMIT() asm volatile("cp.async.commit_group;" ::: "memory")
#define CP_WAIT(n)  asm volatile("cp.async.wait_group %0;" :: "n"(n) : "memory")

// m16n8k16 fp16 row.col, fp32 accum
__device__ __forceinline__ void mma16(float* cc, const uint4& a, const uint2& b) {
    asm volatile(
        "mma.sync.aligned.m16n8k16.row.col.f32.f16.f16.f32 "
        "{%0,%1,%2,%3}, {%4,%5,%6,%7}, {%8,%9}, {%0,%1,%2,%3};"
        : "+f"(cc[0]), "+f"(cc[1]), "+f"(cc[2]), "+f"(cc[3])
        : "r"(a.x), "r"(a.y), "r"(a.z), "r"(a.w), "r"(b.x), "r"(b.y));
}

// ---------------- prep: src[K][M] fp32 -> A-frag fp16 tiles ----------------
// A[m][k] = src[k][m]. Per tile (128x32): uint4 f = (mb*2+ks)*32+lane, mb in [0,8), ks in [0,2):
//   .x = {A[mb*16+r][kb], A[..][kb+1]}  .y = rows+8  .z = k+8  .w = rows+8,k+8   (kb = ks*16+2c)
__global__ void prep_w_kernel(const float* __restrict__ src, uint4* __restrict__ dst,
                              int R, int C, int Mtiles, int Kchunks) {
    __shared__ float ts[32][132];
    int e = blockIdx.z, mt = blockIdx.y, kc = blockIdx.x;
    int tid = threadIdx.x;
    const float* sp = src + (size_t)e * R * C + (size_t)(kc * 32) * C + mt * 128;
#pragma unroll
    for (int i = 0; i < 16; i++) {
        int idx = tid + i * 256;
        int kk = idx >> 7, mm = idx & 127;
        ts[kk][mm] = sp[(size_t)kk * C + mm];
    }
    __syncthreads();
    uint4* dp = dst + ((size_t)(e * Mtiles + mt) * Kchunks + kc) * 512;
#pragma unroll
    for (int i = 0; i < 2; i++) {
        int f = tid + i * 256;
        int lane = f & 31, ks = (f >> 5) & 1, mb = f >> 6;
        int r = lane >> 2, c = lane & 3;
        int kb = ks * 16 + 2 * c;
        int m0 = mb * 16 + r;
        uint4 v;
        v.x = pack2(ts[kb][m0],     ts[kb + 1][m0]);
        v.y = pack2(ts[kb][m0 + 8], ts[kb + 1][m0 + 8]);
        v.z = pack2(ts[kb + 8][m0],     ts[kb + 9][m0]);
        v.w = pack2(ts[kb + 8][m0 + 8], ts[kb + 9][m0 + 8]);
        dp[f] = v;
    }
}

// ---------------- prep: x[t][k] fp32 -> B-frag fp16 tiles ----------------
// Per tile (128x32): uint2 f = (n8*2+ks)*32+lane, n8 in [0,16):
//   .x = {B[tt][kb], B[tt][kb+1]}  .y = {B[tt][kb+8], B[tt][kb+9]}   (tt = n8*8 + (lane>>2))
__global__ void prep_x_kernel(const float* __restrict__ src, uint2* __restrict__ dst) {
    __shared__ float ts[128][33];
    int e = blockIdx.z, tb = blockIdx.y, kc = blockIdx.x;
    int tid = threadIdx.x;
    const float* sp = src + (size_t)e * T_ * DIN_ + (size_t)(tb * 128) * DIN_ + kc * 32;
#pragma unroll
    for (int i = 0; i < 16; i++) {
        int idx = tid + i * 256;
        int tt = idx >> 5, kk = idx & 31;
        ts[tt][kk] = sp[(size_t)tt * DIN_ + kk];
    }
    __syncthreads();
    uint2* dp = dst + ((size_t)(e * TTILES + tb) * KC1 + kc) * 1024;
#pragma unroll
    for (int i = 0; i < 4; i++) {
        int f = tid + i * 256;
        int lane = f & 31, ks = (f >> 5) & 1, n8 = f >> 6;
        int rl = lane >> 2, c = lane & 3;
        int tt = n8 * 8 + rl, kb = ks * 16 + 2 * c;
        uint2 v;
        v.x = pack2(ts[tt][kb],     ts[tt][kb + 1]);
        v.y = pack2(ts[tt][kb + 8], ts[tt][kb + 9]);
        dp[f] = v;
    }
}

// ---------------- k1: fused gate+down GEMM + SwiGLU -> h frag (fp16) --------
// smem per stage: Ag(8KB) Ad(8KB) B(8KB) = 24KB; 2 stages = 48KB
#define K1_STAGE_U 6144
__global__ __launch_bounds__(256, 1) void k1_gemm(const uint32_t* __restrict__ xf,
                                                  const uint32_t* __restrict__ gF,
                                                  const uint32_t* __restrict__ dF,
                                                  uint32_t* __restrict__ hf) {
    extern __shared__ uint32_t sm[];
    int tid = threadIdx.x, lane = tid & 31, wid = tid >> 5;
    int wm = wid & 1, wn = wid >> 1;        // 2(M) x 4(N) warp grid, warp tile 64x32
    int r = lane >> 2, c = lane & 3;

    int bid = blockIdx.x;
    int e = bid / (HTILES * TTILES);
    int rem = bid % (HTILES * TTILES);
    int ht = rem >> 4;
    int tb = rem & 15;
    int h0 = ht * 128;

    const uint32_t* gp = gF + ((size_t)(e * HTILES + ht) * KC1) * ATILE_U;
    const uint32_t* dp = dF + ((size_t)(e * HTILES + ht) * KC1) * ATILE_U;
    const uint32_t* xp = xf + ((size_t)(e * TTILES + tb) * KC1) * BTILE_U;

    float ag[4][4][4], ad[4][4][4];
#pragma unroll
    for (int mt = 0; mt < 4; mt++)
#pragma unroll
        for (int nt = 0; nt < 4; nt++)
#pragma unroll
            for (int k = 0; k < 4; k++) { ag[mt][nt][k] = 0.f; ad[mt][nt][k] = 0.f; }

    uint32_t sbase = smem_u32(sm);

    auto fill = [&](int s, int kc) {
        uint32_t stb = sbase + (uint32_t)(s * K1_STAGE_U * 4);
        const uint4* ga = (const uint4*)(gp + (size_t)kc * ATILE_U);
        const uint4* da = (const uint4*)(dp + (size_t)kc * ATILE_U);
        const uint4* xa = (const uint4*)(xp + (size_t)kc * BTILE_U);
#pragma unroll
        for (int i = 0; i < 6; i++) {
            int idx = tid + i * 256;                 // 0..1535 uint4s
            if (idx < 512)       cp16(stb + idx * 16, ga + idx);
            else if (idx < 1024) cp16(stb + idx * 16, da + (idx - 512));
            else                 cp16(stb + idx * 16, xa + (idx - 1024));
        }
    };

    auto compute = [&](int s) {
        const uint32_t* stg = sm + s * K1_STAGE_U;
        const uint4* Ag = (const uint4*)stg;
        const uint4* Ad = (const uint4*)(stg + 2048);
        const uint2* Bx = (const uint2*)(stg + 4096);
#pragma unroll
        for (int ks = 0; ks < 2; ks++) {
            uint2 bf[4];
#pragma unroll
            for (int nt = 0; nt < 4; nt++)
                bf[nt] = Bx[((wn * 4 + nt) * 2 + ks) * 32 + lane];
            uint4 af[4];
#pragma unroll
            for (int mt = 0; mt < 4; mt++)
                af[mt] = Ag[((wm * 4 + mt) * 2 + ks) * 32 + lane];
#pragma unroll
            for (int mt = 0; mt < 4; mt++)
#pragma unroll
                for (int nt = 0; nt < 4; nt++) mma16(ag[mt][nt], af[mt], bf[nt]);
#pragma unroll
            for (int mt = 0; mt < 4; mt++)
                af[mt] = Ad[((wm * 4 + mt) * 2 + ks) * 32 + lane];
#pragma unroll
            for (int mt = 0; mt < 4; mt++)
#pragma unroll
                for (int nt = 0; nt < 4; nt++) mma16(ad[mt][nt], af[mt], bf[nt]);
        }
    };

    fill(0, 0); CP_COMMIT();
    for (int kc = 0; kc < KC1; kc++) {
        if (kc + 1 < KC1) { fill((kc + 1) & 1, kc + 1); CP_COMMIT(); CP_WAIT(1); }
        else              { CP_WAIT(0); }
        __syncthreads();
        compute(kc & 1);
        __syncthreads();
    }

    // SwiGLU epilogue -> hf in k2 B-frag fp16 layout.
    // h = h0 + wm*64 + mt*16 + r + (q>>1)*8 ; t = (wn*4+nt)*8 + 2c + (q&1)
    // kc2 = h>>5 = h0/32 + wm*2 + (mt>>1); ks2 = mt&1; j = q>>1; kin parity = r parity
    uint32_t* hb = hf + ((size_t)(e * TTILES + tb) * KC2) * BTILE_U;
#pragma unroll
    for (int mt = 0; mt < 4; mt++) {
        int kc2 = (h0 >> 5) + wm * 2 + (mt >> 1);
        int ks2 = mt & 1;
        uint32_t* base = hb + (size_t)kc2 * BTILE_U;
#pragma unroll
        for (int nt = 0; nt < 4; nt++) {
            int n8 = wn * 4 + nt;
#pragma unroll
            for (int q = 0; q < 4; q++) {
                float g = ag[mt][nt][q], u = ad[mt][nt][q];
                float v = g / (1.0f + __expf(-g)) * u;
                float pv = __shfl_xor_sync(0xffffffffu, v, 4);   // partner: r^1
                if (!(r & 1)) {
                    int lane2 = (2 * c + (q & 1)) * 4 + (r >> 1);
                    int fidx = (n8 * 2 + ks2) * 32 + lane2;
                    base[fidx * 2 + (q >> 1)] = pack2(v, pv);
                }
            }
        }
    }
}

// ---------------- k2: out[t,d] = sum_h h[t,h] * up[h,d] -------------------
// smem per stage: A(8KB) B(8KB) = 16KB; 2 stages = 32KB -> 2 CTAs/SM
#define K2_STAGE_U 4096
__global__ __launch_bounds__(256, 2) void k2_gemm(const uint32_t* __restrict__ hf,
                                                  const uint32_t* __restrict__ uF,
                                                  float* __restrict__ out) {
    extern __shared__ uint32_t sm[];
    int tid = threadIdx.x, lane = tid & 31, wid = tid >> 5;
    int wm = wid & 1, wn = wid >> 1;
    int r = lane >> 2, c = lane & 3;

    int bid = blockIdx.x;
    int e = bid / (DTILES * TTILES);
    int rem = bid % (DTILES * TTILES);
    int dt = rem >> 4;
    int tb = rem & 15;
    int d0 = dt * 128, t0 = tb * 128;

    const uint32_t* up = uF + ((size_t)(e * DTILES + dt) * KC2) * ATILE_U;
    const uint32_t* hp = hf + ((size_t)(e * TTILES + tb) * KC2) * BTILE_U;

    float acc[4][4][4];
#pragma unroll
    for (int mt = 0; mt < 4; mt++)
#pragma unroll
        for (int nt = 0; nt < 4; nt++)
#pragma unroll
            for (int k = 0; k < 4; k++) acc[mt][nt][k] = 0.f;

    uint32_t sbase = smem_u32(sm);

    auto fill = [&](int s, int kc) {
        uint32_t stb = sbase + (uint32_t)(s * K2_STAGE_U * 4);
        const uint4* ua = (const uint4*)(up + (size_t)kc * ATILE_U);
        const uint4* ha = (const uint4*)(hp + (size_t)kc * BTILE_U);
#pragma unroll
        for (int i = 0; i < 4; i++) {
            int idx = tid + i * 256;                 // 0..1023 uint4s
            if (idx < 512) cp16(stb + idx * 16, ua + idx);
            else           cp16(stb + idx * 16, ha + (idx - 512));
        }
    };

    auto compute = [&](int s) {
        const uint32_t* stg = sm + s * K2_STAGE_U;
        const uint4* A = (const uint4*)stg;
        const uint2* B = (const uint2*)(stg + 2048);
#pragma unroll
        for (int ks = 0; ks < 2; ks++) {
            uint2 bf[4];
#pragma unroll
            for (int nt = 0; nt < 4; nt++)
                bf[nt] = B[((wn * 4 + nt) * 2 + ks) * 32 + lane];
            uint4 af[4];
#pragma unroll
            for (int mt = 0; mt < 4; mt++)
                af[mt] = A[((wm * 4 + mt) * 2 + ks) * 32 + lane];
#pragma unroll
            for (int mt = 0; mt < 4; mt++)
#pragma unroll
                for (int nt = 0; nt < 4; nt++) mma16(acc[mt][nt], af[mt], bf[nt]);
        }
    };

    fill(0, 0); CP_COMMIT();
    for (int kc = 0; kc < KC2; kc++) {
        if (kc + 1 < KC2) { fill((kc + 1) & 1, kc + 1); CP_COMMIT(); CP_WAIT(1); }
        else              { CP_WAIT(0); }
        __syncthreads();
        compute(kc & 1);
        __syncthreads();
    }

    float* ob = out + (size_t)e * T_ * DIN_;
#pragma unroll
    for (int mt = 0; mt < 4; mt++)
#pragma unroll
        for (int nt = 0; nt < 4; nt++) {
            int t = t0 + (wn * 4 + nt) * 8 + 2 * c;
#pragma unroll
            for (int h2 = 0; h2 < 2; h2++) {
                int dg = d0 + wm * 64 + mt * 16 + r + h2 * 8;
                ob[(size_t)t * DIN_ + dg]       = acc[mt][nt][h2 * 2 + 0];
                ob[(size_t)(t + 1) * DIN_ + dg] = acc[mt][nt][h2 * 2 + 1];
            }
        }
}

// ---------------- launch ----------------
extern "C" void kernel_launch(void* const* d_in, const int* in_sizes, int n_in,
                              void* d_out, int out_size) {
    const float* x    = (const float*)d_in[0];
    const float* gate = (const float*)d_in[1];
    const float* down = (const float*)d_in[2];
    const float* up   = (const float*)d_in[3];
    float* out = (float*)d_out;

    uint32_t *gF, *dF, *uF, *xF, *hF;
    cudaGetSymbolAddress((void**)&gF, g_wfG);
    cudaGetSymbolAddress((void**)&dF, g_wfD);
    cudaGetSymbolAddress((void**)&uF, g_wfU);
    cudaGetSymbolAddress((void**)&xF, g_xf);
    cudaGetSymbolAddress((void**)&hF, g_hf);

    const int k1_smem = 2 * K1_STAGE_U * 4;   // 49152
    const int k2_smem = 2 * K2_STAGE_U * 4;   // 32768
    cudaFuncSetAttribute(k1_gemm, cudaFuncAttributeMaxDynamicSharedMemorySize, k1_smem);
    cudaFuncSetAttribute(k2_gemm, cudaFuncAttributeMaxDynamicSharedMemorySize, k2_smem);

    // order chosen so k1 sits at launch index 3 (the slot ncu has been profiling)
    prep_w_kernel<<<dim3(KC1, HTILES, E_), 256>>>(gate, (uint4*)gF, DIN_, H_, HTILES, KC1);
    prep_w_kernel<<<dim3(KC1, HTILES, E_), 256>>>(down, (uint4*)dF, DIN_, H_, HTILES, KC1);
    prep_x_kernel<<<dim3(KC1, TTILES, E_), 256>>>(x, (uint2*)xF);
    k1_gemm<<<E_ * HTILES * TTILES, 256, k1_smem>>>(xF, gF, dF, hF);
    prep_w_kernel<<<dim3(KC2, DTILES, E_), 256>>>(up, (uint4*)uF, H_, DIN_, DTILES, KC2);
    k2_gemm<<<E_ * DTILES * TTILES, 256, k2_smem>>>(hF, uF, out);
}